// round 16
// baseline (speedup 1.0000x reference)
#include <cuda_runtime.h>
#include <math.h>

#define D_MODEL 512
#define HEADS   8
#define HDIM    64
#define NSEQ    1024
#define TOPK    102
#define MAXM    2048   // B*N for B=2

// ---------------- scratch (static device globals; no allocs) ----------------
__device__ float g_QKV[3u * MAXM * D_MODEL];     // Q | K | V, each [M,512]
__device__ float g_att[MAXM * D_MODEL];          // attention output pre-Wo
__device__ float g_part[4u * MAXM * D_MODEL];    // split-K partials for Wo GEMM
__device__ float g_qkvpart[2u * 3u * MAXM * D_MODEL];  // split-K2 partials for QKV
__device__ unsigned char g_qh[MAXM * HEADS];
__device__ unsigned char g_kh[MAXM * HEADS];
__device__ float g_qn[MAXM * HEADS];             // |q|^2 per (b,h,n)
__device__ float g_kn[MAXM * HEADS];             // |k|^2 per (b,h,n)

// ---------------- SGEMM: C = A[M,512] * W[512,512]^T ----------------
// 128x128 block tile, 256 threads, 8x8 microtile, BK=16, reg-prefetch (R14 proven)
#define GBM 128
#define GBN 128
#define GBK 16

__device__ __forceinline__ void gemm_body(
    const float* __restrict__ A, const float* __restrict__ W,
    float* __restrict__ C, int bm, int bn, int kbeg, int kend)
{
    __shared__ __align__(16) float As[GBK][GBM];   // 8 KB
    __shared__ __align__(16) float Bs[GBK][GBN];   // 8 KB

    int tid  = threadIdx.x;
    int trow = tid >> 4;          // 0..15 -> rows trow*8
    int tcol = tid & 15;          // 0..15 -> cols tcol*8
    int lrow = tid >> 1;          // 0..127
    int lkc  = (tid & 1) << 3;    // 0,8

    const float* Aptr = &A[(size_t)(bm + lrow) * D_MODEL + lkc];
    const float* Wptr = &W[(size_t)(bn + lrow) * D_MODEL + lkc];

    float acc[8][8] = {};

    float4 a0 = *reinterpret_cast<const float4*>(Aptr + kbeg);
    float4 a1 = *reinterpret_cast<const float4*>(Aptr + kbeg + 4);
    float4 w0 = *reinterpret_cast<const float4*>(Wptr + kbeg);
    float4 w1 = *reinterpret_cast<const float4*>(Wptr + kbeg + 4);

    for (int k0 = kbeg; k0 < kend; k0 += GBK) {
#pragma unroll
        for (int i = 0; i < 4; ++i) {
            As[lkc + i][lrow]     = (&a0.x)[i];
            As[lkc + 4 + i][lrow] = (&a1.x)[i];
            Bs[lkc + i][lrow]     = (&w0.x)[i];
            Bs[lkc + 4 + i][lrow] = (&w1.x)[i];
        }
        __syncthreads();

        int kn = k0 + GBK;
        if (kn < kend) {
            a0 = *reinterpret_cast<const float4*>(Aptr + kn);
            a1 = *reinterpret_cast<const float4*>(Aptr + kn + 4);
            w0 = *reinterpret_cast<const float4*>(Wptr + kn);
            w1 = *reinterpret_cast<const float4*>(Wptr + kn + 4);
        }

#pragma unroll
        for (int k = 0; k < GBK; ++k) {
            float4 af0 = *reinterpret_cast<const float4*>(&As[k][trow * 8]);
            float4 af1 = *reinterpret_cast<const float4*>(&As[k][trow * 8 + 4]);
            float4 bf0 = *reinterpret_cast<const float4*>(&Bs[k][tcol * 8]);
            float4 bf1 = *reinterpret_cast<const float4*>(&Bs[k][tcol * 8 + 4]);
            float ar[8] = {af0.x, af0.y, af0.z, af0.w, af1.x, af1.y, af1.z, af1.w};
            float br[8] = {bf0.x, bf0.y, bf0.z, bf0.w, bf1.x, bf1.y, bf1.z, bf1.w};
#pragma unroll
            for (int i = 0; i < 8; ++i)
#pragma unroll
                for (int j = 0; j < 8; ++j)
                    acc[i][j] = fmaf(ar[i], br[j], acc[i][j]);
        }
        __syncthreads();
    }
#pragma unroll
    for (int i = 0; i < 8; ++i) {
        float* dst = &C[(size_t)(bm + trow * 8 + i) * D_MODEL + bn + tcol * 8];
        *reinterpret_cast<float4*>(dst) =
            make_float4(acc[i][0], acc[i][1], acc[i][2], acc[i][3]);
        *reinterpret_cast<float4*>(dst + 4) =
            make_float4(acc[i][4], acc[i][5], acc[i][6], acc[i][7]);
    }
}

// QKV split-K2 (R14 proven): z selects K half
__global__ __launch_bounds__(256, 2) void gemm_qkv_kernel(
    const float* __restrict__ A,
    const float* __restrict__ Wq, const float* __restrict__ Wk,
    const float* __restrict__ Wv, int M)
{
    int gn    = blockIdx.y * GBN;           // [0,1536)
    int which = gn >> 9;
    int bn    = gn & 511;
    int z     = blockIdx.z;
    const float* W = (which == 0) ? Wq : (which == 1) ? Wk : Wv;
    float* P = g_qkvpart + ((size_t)z * 3 + which) * M * D_MODEL;
    gemm_body(A, W, P, blockIdx.x * GBM, bn,
              z * (D_MODEL / 2), (z + 1) * (D_MODEL / 2));
}

__global__ __launch_bounds__(256) void add_qkv_kernel(int n4)
{
    int i = blockIdx.x * blockDim.x + threadIdx.x;
    if (i >= n4) return;
    const float4* p = reinterpret_cast<const float4*>(g_qkvpart);
    float4 a = p[i], b = p[i + n4];
    reinterpret_cast<float4*>(g_QKV)[i] =
        make_float4(a.x + b.x, a.y + b.y, a.z + b.z, a.w + b.w);
}

__global__ __launch_bounds__(256, 2) void gemm_o_kernel(
    const float* __restrict__ Wo, int M)
{
    int z = blockIdx.z;
    float* P = g_part + (size_t)z * M * D_MODEL;
    gemm_body(g_att, Wo, P, blockIdx.x * GBM, blockIdx.y * GBN,
              z * (D_MODEL / 4), (z + 1) * (D_MODEL / 4));
}

__global__ __launch_bounds__(256) void add_kernel(float* __restrict__ out, int n4)
{
    int i = blockIdx.x * blockDim.x + threadIdx.x;
    if (i >= n4) return;
    const float4* p = reinterpret_cast<const float4*>(g_part);
    float4 a = p[i], b = p[i + n4], c = p[i + 2 * n4], d = p[i + 3 * n4];
    reinterpret_cast<float4*>(out)[i] =
        make_float4((a.x + b.x) + (c.x + d.x), (a.y + b.y) + (c.y + d.y),
                    (a.z + b.z) + (c.z + d.z), (a.w + b.w) + (c.w + d.w));
}

// ---------------- LSH hashes + norms ----------------
__global__ __launch_bounds__(256) void hash_kernel(const float* __restrict__ rv, int M)
{
    __shared__ float rs[HEADS * HDIM];
    for (int i = threadIdx.x; i < HEADS * HDIM; i += blockDim.x) rs[i] = rv[i];
    __syncthreads();

    int idx = blockIdx.x * blockDim.x + threadIdx.x;
    int total = 2 * M * HEADS;
    if (idx >= total) return;
    int isK = (idx >= M * HEADS) ? 1 : 0;
    int r = idx - isK * M * HEADS;
    int row = r >> 3;
    int h   = r & 7;

    const float4* src4 = reinterpret_cast<const float4*>(
        g_QKV + (size_t)isK * M * D_MODEL + (size_t)row * D_MODEL + h * HDIM);
    float dacc[8] = {};
    float n0 = 0.f, n1 = 0.f, n2 = 0.f, n3 = 0.f;
#pragma unroll
    for (int c4 = 0; c4 < HDIM / 4; ++c4) {
        float4 xv = src4[c4];
        n0 = fmaf(xv.x, xv.x, n0); n1 = fmaf(xv.y, xv.y, n1);
        n2 = fmaf(xv.z, xv.z, n2); n3 = fmaf(xv.w, xv.w, n3);
#pragma unroll
        for (int k = 0; k < 8; ++k) {
            const float* rk = &rs[k * HDIM + c4 * 4];
            dacc[k] = fmaf(xv.x, rk[0], dacc[k]);
            dacc[k] = fmaf(xv.y, rk[1], dacc[k]);
            dacc[k] = fmaf(xv.z, rk[2], dacc[k]);
            dacc[k] = fmaf(xv.w, rk[3], dacc[k]);
        }
    }
    float nrm = (n0 + n1) + (n2 + n3);
    unsigned int bits = 0;
#pragma unroll
    for (int k = 0; k < 8; ++k) bits |= (dacc[k] >= 0.f ? 1u : 0u) << k;
    int bhn = ((row >> 10) * HEADS + h) * NSEQ + (row & (NSEQ - 1));
    if (isK) { g_kh[bhn] = (unsigned char)bits; g_kn[bhn] = nrm; }
    else     { g_qh[bhn] = (unsigned char)bits; g_qn[bhn] = nrm; }
}

// ---------------- sparse hyperbolic attention: one block per (b,h,n) ----------------
// 8-lane-group partitioning for BOTH dot and V passes; closed-form weight.
__global__ __launch_bounds__(128) void attn_kernel(int M)
{
    const int PER = NSEQ / 128;          // 8 contiguous j per thread
    int gid = blockIdx.x;
    int n  = gid & (NSEQ - 1);
    int bh = gid >> 10;
    int h = bh & 7, b = bh >> 3;

    const float* Q = g_QKV;
    const float* K = g_QKV + (size_t)M * D_MODEL;
    const float* V = g_QKV + 2 * (size_t)M * D_MODEL;

    __shared__ float sc[TOPK + 2];       // dots -> weights (pad slots 102/103)
    __shared__ short selj[TOPK];
    __shared__ int whist[4][10];         // [warp][bucket], slot 9 = dead pad
    __shared__ int wsum[4];              // packed (gt<<16 | eq) per warp
    __shared__ float wpart[16];          // per-group weight sums
    __shared__ __align__(16) float ored[16][HDIM];   // 16 group partials

    int tid = threadIdx.x, lane = tid & 31, warp = tid >> 5;
    int grp = lane >> 3;                 // group 0..3 (8 lanes each)
    int gl  = lane & 7;                  // lane within group
    int gidx = warp * 4 + grp;           // global group 0..15

    size_t rowbase = (size_t)b * NSEQ * D_MODEL + h * HDIM;
    const float* qrow = Q + rowbase + (size_t)n * D_MODEL;
    float4 qr0 = *reinterpret_cast<const float4*>(qrow + gl * 8);
    float4 qr1 = *reinterpret_cast<const float4*>(qrow + gl * 8 + 4);

    // --- hash match counts for my 8 contiguous keys ---
    unsigned int qb = g_qh[bh * NSEQ + n];
    float qn = g_qn[bh * NSEQ + n];
    const unsigned char* khb = g_kh + bh * NSEQ;
    int base = tid * PER;
    uint2 kv8 = *reinterpret_cast<const uint2*>(khb + base);
    int m[PER];
#pragma unroll
    for (int i = 0; i < PER; ++i) {
        unsigned int byte = ((i < 4 ? kv8.x >> (8 * i) : kv8.y >> (8 * (i - 4))) & 0xFFu);
        m[i] = 8 - __popc(byte ^ qb);
    }

    // --- packed per-warp histogram: buckets (2vp, 2vp+1) in one redux ---
#pragma unroll
    for (int vp = 0; vp < 5; ++vp) {
        int v0 = 2 * vp, v1 = 2 * vp + 1;   // v1==9 never matches (m<=8)
        int c = 0;
#pragma unroll
        for (int i = 0; i < PER; ++i) {
            c += (m[i] == v0) ? 0x10000 : 0;
            c += (m[i] == v1) ? 1 : 0;
        }
        c = __reduce_add_sync(0xffffffffu, c);
        if (lane == vp) {
            whist[warp][v0] = c >> 16;
            whist[warp][v1] = c & 0xFFFF;   // slot 9 = dead pad
        }
    }
    __syncthreads();   // (1) whist ready

    // --- uniform threshold in registers ---
    int t = 0, need = TOPK;
    {
        int cum = 0;
#pragma unroll
        for (int v = 8; v >= 0; --v) {
            int hv = whist[0][v] + whist[1][v] + whist[2][v] + whist[3][v];
            int ncum = cum + hv;
            if (cum < TOPK && ncum >= TOPK) { t = v; need = TOPK - cum; }
            cum = ncum;
        }
    }
    int ngt = TOPK - need;

    // --- packed selection scan: (cgt<<16 | ceq), one shuffle scan ---
    int cgt = 0, ceq = 0;
#pragma unroll
    for (int i = 0; i < PER; ++i) { cgt += (m[i] > t); ceq += (m[i] == t); }
    int pk = (cgt << 16) | ceq;
    int spk = pk;
#pragma unroll
    for (int o = 1; o < 32; o <<= 1) {
        int a = __shfl_up_sync(0xffffffffu, spk, o); if (lane >= o) spk += a;
    }
    if (lane == 31) wsum[warp] = spk;
    __syncthreads();   // (2) wsum ready
    int rank = spk - pk;
#pragma unroll
    for (int w = 0; w < 4; ++w) if (w < warp) rank += wsum[w];
    int rgt = rank >> 16, req = rank & 0xFFFF;
#pragma unroll
    for (int i = 0; i < PER; ++i) {
        int j = base + i;
        if (m[i] > t) selj[rgt++] = (short)j;
        else if (m[i] == t) { if (req < need) selj[ngt + req] = (short)j; req++; }
    }
    __syncthreads();   // (3) selj ready

    // --- coalesced dot pass: 8-lane group per key row, 3-shuffle reduce ---
    const float* Kb = K + rowbase;
#pragma unroll
    for (int i = 0; i < 7; ++i) {
        int s = gidx + 16 * i;               // 0..111, unique per (group, i)
        bool ok = (s < TOPK);
        int j = ok ? (int)selj[s] : 0;
        int joff = j << 9;                   // j * D_MODEL
        const float* kr = Kb + joff + gl * 8;
        float4 k0 = *reinterpret_cast<const float4*>(kr);
        float4 k1 = *reinterpret_cast<const float4*>(kr + 4);
        float part = fmaf(qr0.x, k0.x,
                     fmaf(qr0.y, k0.y,
                     fmaf(qr0.z, k0.z,
                     fmaf(qr0.w, k0.w,
                     fmaf(qr1.x, k1.x,
                     fmaf(qr1.y, k1.y,
                     fmaf(qr1.z, k1.z, qr1.w * k1.w)))))));
#pragma unroll
        for (int o = 1; o < 8; o <<= 1)
            part += __shfl_xor_sync(0xffffffffu, part, o);
        if (gl == 0) sc[ok ? s : TOPK] = part;   // dead-slot write for s>=TOPK
    }
    __syncthreads();   // (4) dots ready

    // --- score + weight, all threads parallel; closed-form exp(-acosh) ---
    if (tid < TOPK) {
        float dot = sc[tid];
        int j = selj[tid];
        float kn = g_kn[bh * NSEQ + j];
        float dsq = qn + kn - 2.f * dot;
        float denom = fmaxf((1.f - qn) * (1.f - kn), 1e-6f);
        float ca = fmaxf(1.f + 2.f * dsq / denom, 1.f);
        // exp(-acosh(ca)) == 1 / (ca + sqrt(ca^2 - 1)), exact
        sc[tid] = 1.f / (ca + sqrtf(fmaf(ca, ca, -1.f)));
    }
    __syncthreads();   // (5) weights ready

    // --- weighted V sum + weight-sum: 8-lane group per key row, 7 iters ---
    const float* Vb = V + rowbase;
    float4 acc0 = make_float4(0.f, 0.f, 0.f, 0.f);
    float4 acc1 = make_float4(0.f, 0.f, 0.f, 0.f);
    float wacc = 0.f;
#pragma unroll
    for (int i = 0; i < 7; ++i) {
        int s = gidx + 16 * i;
        bool ok = (s < TOPK);
        int j = ok ? (int)selj[s] : 0;
        int joff = j << 9;
        float w = ok ? sc[s] : 0.f;
        const float* vr = Vb + joff + gl * 8;
        float4 v0 = *reinterpret_cast<const float4*>(vr);
        float4 v1 = *reinterpret_cast<const float4*>(vr + 4);
        acc0.x = fmaf(w, v0.x, acc0.x); acc0.y = fmaf(w, v0.y, acc0.y);
        acc0.z = fmaf(w, v0.z, acc0.z); acc0.w = fmaf(w, v0.w, acc0.w);
        acc1.x = fmaf(w, v1.x, acc1.x); acc1.y = fmaf(w, v1.y, acc1.y);
        acc1.z = fmaf(w, v1.z, acc1.z); acc1.w = fmaf(w, v1.w, acc1.w);
        wacc += w;
    }
    *reinterpret_cast<float4*>(&ored[gidx][gl * 8])     = acc0;
    *reinterpret_cast<float4*>(&ored[gidx][gl * 8 + 4]) = acc1;
    if (gl == 0) wpart[gidx] = wacc;
    __syncthreads();   // (6) partials ready
    if (tid < HDIM) {
        float s0 = (ored[0][tid]  + ored[1][tid])  + (ored[2][tid]  + ored[3][tid]);
        float s1 = (ored[4][tid]  + ored[5][tid])  + (ored[6][tid]  + ored[7][tid]);
        float s2 = (ored[8][tid]  + ored[9][tid])  + (ored[10][tid] + ored[11][tid]);
        float s3 = (ored[12][tid] + ored[13][tid]) + (ored[14][tid] + ored[15][tid]);
        float w0 = (wpart[0] + wpart[1]) + (wpart[2] + wpart[3]);
        float w1 = (wpart[4] + wpart[5]) + (wpart[6] + wpart[7]);
        float w2 = (wpart[8] + wpart[9]) + (wpart[10] + wpart[11]);
        float w3 = (wpart[12] + wpart[13]) + (wpart[14] + wpart[15]);
        g_att[((size_t)(b * NSEQ + n)) * D_MODEL + h * HDIM + tid] =
            ((s0 + s1) + (s2 + s3)) / ((w0 + w1) + (w2 + w3));
    }
}

// ---------------- entry ----------------
extern "C" void kernel_launch(void* const* d_in, const int* in_sizes, int n_in,
                              void* d_out, int out_size)
{
    const float* x  = (const float*)d_in[0];
    const float* Wq = (const float*)d_in[1];
    const float* Wk = (const float*)d_in[2];
    const float* Wv = (const float*)d_in[3];
    const float* Wo = (const float*)d_in[4];
    const float* rv = (const float*)d_in[5];
    float* out = (float*)d_out;

    int M = in_sizes[0] / D_MODEL;   // B*N = 2048

    dim3 gq(M / GBM, (3 * D_MODEL) / GBN, 2); // (16, 12, 2) = 384 blocks
    gemm_qkv_kernel<<<gq, 256>>>(x, Wq, Wk, Wv, M);

    int nq4 = 3 * M * D_MODEL / 4;
    add_qkv_kernel<<<(nq4 + 255) / 256, 256>>>(nq4);

    int hthreads = 2 * M * HEADS;
    hash_kernel<<<(hthreads + 255) / 256, 256>>>(rv, M);

    attn_kernel<<<M * HEADS, 128>>>(M);       // 16384 blocks

    dim3 go(M / GBM, D_MODEL / GBN, 4);       // (16, 4, 4) = 256 blocks
    gemm_o_kernel<<<go, 256>>>(Wo, M);

    int n4 = M * D_MODEL / 4;
    add_kernel<<<(n4 + 255) / 256, 256>>>(out, n4);
}

// round 17
// speedup vs baseline: 1.0439x; 1.0439x over previous
#include <cuda_runtime.h>
#include <math.h>

#define D_MODEL 512
#define HEADS   8
#define HDIM    64
#define NSEQ    1024
#define TOPK    102
#define MAXM    2048   // B*N for B=2

// ---------------- scratch (static device globals; no allocs) ----------------
__device__ float g_QKV[3u * MAXM * D_MODEL];     // Q | K | V, each [M,512]
__device__ float g_att[MAXM * D_MODEL];          // attention output pre-Wo
__device__ float g_part[4u * MAXM * D_MODEL];    // split-K partials for Wo GEMM
__device__ float g_qkvpart[2u * 3u * MAXM * D_MODEL];  // split-K2 partials for QKV
__device__ unsigned char g_qh[MAXM * HEADS];
__device__ unsigned char g_kh[MAXM * HEADS];
__device__ float g_qn[MAXM * HEADS];             // |q|^2 per (b,h,n)
__device__ float g_kn[MAXM * HEADS];             // |k|^2 per (b,h,n)

// ---------------- SGEMM: C = A[M,512] * W[512,512]^T ----------------
// 128x128 block tile, 256 threads, 8x8 microtile, BK=16, reg-prefetch (R14 proven)
#define GBM 128
#define GBN 128
#define GBK 16

__device__ __forceinline__ void gemm_body(
    const float* __restrict__ A, const float* __restrict__ W,
    float* __restrict__ C, int bm, int bn, int kbeg, int kend)
{
    __shared__ __align__(16) float As[GBK][GBM];   // 8 KB
    __shared__ __align__(16) float Bs[GBK][GBN];   // 8 KB

    int tid  = threadIdx.x;
    int trow = tid >> 4;          // 0..15 -> rows trow*8
    int tcol = tid & 15;          // 0..15 -> cols tcol*8
    int lrow = tid >> 1;          // 0..127
    int lkc  = (tid & 1) << 3;    // 0,8

    const float* Aptr = &A[(size_t)(bm + lrow) * D_MODEL + lkc];
    const float* Wptr = &W[(size_t)(bn + lrow) * D_MODEL + lkc];

    float acc[8][8] = {};

    float4 a0 = *reinterpret_cast<const float4*>(Aptr + kbeg);
    float4 a1 = *reinterpret_cast<const float4*>(Aptr + kbeg + 4);
    float4 w0 = *reinterpret_cast<const float4*>(Wptr + kbeg);
    float4 w1 = *reinterpret_cast<const float4*>(Wptr + kbeg + 4);

    for (int k0 = kbeg; k0 < kend; k0 += GBK) {
#pragma unroll
        for (int i = 0; i < 4; ++i) {
            As[lkc + i][lrow]     = (&a0.x)[i];
            As[lkc + 4 + i][lrow] = (&a1.x)[i];
            Bs[lkc + i][lrow]     = (&w0.x)[i];
            Bs[lkc + 4 + i][lrow] = (&w1.x)[i];
        }
        __syncthreads();

        int kn = k0 + GBK;
        if (kn < kend) {
            a0 = *reinterpret_cast<const float4*>(Aptr + kn);
            a1 = *reinterpret_cast<const float4*>(Aptr + kn + 4);
            w0 = *reinterpret_cast<const float4*>(Wptr + kn);
            w1 = *reinterpret_cast<const float4*>(Wptr + kn + 4);
        }

#pragma unroll
        for (int k = 0; k < GBK; ++k) {
            float4 af0 = *reinterpret_cast<const float4*>(&As[k][trow * 8]);
            float4 af1 = *reinterpret_cast<const float4*>(&As[k][trow * 8 + 4]);
            float4 bf0 = *reinterpret_cast<const float4*>(&Bs[k][tcol * 8]);
            float4 bf1 = *reinterpret_cast<const float4*>(&Bs[k][tcol * 8 + 4]);
            float ar[8] = {af0.x, af0.y, af0.z, af0.w, af1.x, af1.y, af1.z, af1.w};
            float br[8] = {bf0.x, bf0.y, bf0.z, bf0.w, bf1.x, bf1.y, bf1.z, bf1.w};
#pragma unroll
            for (int i = 0; i < 8; ++i)
#pragma unroll
                for (int j = 0; j < 8; ++j)
                    acc[i][j] = fmaf(ar[i], br[j], acc[i][j]);
        }
        __syncthreads();
    }
#pragma unroll
    for (int i = 0; i < 8; ++i) {
        float* dst = &C[(size_t)(bm + trow * 8 + i) * D_MODEL + bn + tcol * 8];
        *reinterpret_cast<float4*>(dst) =
            make_float4(acc[i][0], acc[i][1], acc[i][2], acc[i][3]);
        *reinterpret_cast<float4*>(dst + 4) =
            make_float4(acc[i][4], acc[i][5], acc[i][6], acc[i][7]);
    }
}

// QKV split-K2 (R14 proven): z selects K half
__global__ __launch_bounds__(256, 2) void gemm_qkv_kernel(
    const float* __restrict__ A,
    const float* __restrict__ Wq, const float* __restrict__ Wk,
    const float* __restrict__ Wv, int M)
{
    int gn    = blockIdx.y * GBN;           // [0,1536)
    int which = gn >> 9;
    int bn    = gn & 511;
    int z     = blockIdx.z;
    const float* W = (which == 0) ? Wq : (which == 1) ? Wk : Wv;
    float* P = g_qkvpart + ((size_t)z * 3 + which) * M * D_MODEL;
    gemm_body(A, W, P, blockIdx.x * GBM, bn,
              z * (D_MODEL / 2), (z + 1) * (D_MODEL / 2));
}

__global__ __launch_bounds__(256) void add_qkv_kernel(int n4)
{
    int i = blockIdx.x * blockDim.x + threadIdx.x;
    if (i >= n4) return;
    const float4* p = reinterpret_cast<const float4*>(g_qkvpart);
    float4 a = p[i], b = p[i + n4];
    reinterpret_cast<float4*>(g_QKV)[i] =
        make_float4(a.x + b.x, a.y + b.y, a.z + b.z, a.w + b.w);
}

__global__ __launch_bounds__(256, 2) void gemm_o_kernel(
    const float* __restrict__ Wo, int M)
{
    int z = blockIdx.z;
    float* P = g_part + (size_t)z * M * D_MODEL;
    gemm_body(g_att, Wo, P, blockIdx.x * GBM, blockIdx.y * GBN,
              z * (D_MODEL / 4), (z + 1) * (D_MODEL / 4));
}

__global__ __launch_bounds__(256) void add_kernel(float* __restrict__ out, int n4)
{
    int i = blockIdx.x * blockDim.x + threadIdx.x;
    if (i >= n4) return;
    const float4* p = reinterpret_cast<const float4*>(g_part);
    float4 a = p[i], b = p[i + n4], c = p[i + 2 * n4], d = p[i + 3 * n4];
    reinterpret_cast<float4*>(out)[i] =
        make_float4((a.x + b.x) + (c.x + d.x), (a.y + b.y) + (c.y + d.y),
                    (a.z + b.z) + (c.z + d.z), (a.w + b.w) + (c.w + d.w));
}

// ---------------- LSH hashes + norms ----------------
__global__ __launch_bounds__(256) void hash_kernel(const float* __restrict__ rv, int M)
{
    __shared__ float rs[HEADS * HDIM];
    for (int i = threadIdx.x; i < HEADS * HDIM; i += blockDim.x) rs[i] = rv[i];
    __syncthreads();

    int idx = blockIdx.x * blockDim.x + threadIdx.x;
    int total = 2 * M * HEADS;
    if (idx >= total) return;
    int isK = (idx >= M * HEADS) ? 1 : 0;
    int r = idx - isK * M * HEADS;
    int row = r >> 3;
    int h   = r & 7;

    const float4* src4 = reinterpret_cast<const float4*>(
        g_QKV + (size_t)isK * M * D_MODEL + (size_t)row * D_MODEL + h * HDIM);
    float dacc[8] = {};
    float n0 = 0.f, n1 = 0.f, n2 = 0.f, n3 = 0.f;
#pragma unroll
    for (int c4 = 0; c4 < HDIM / 4; ++c4) {
        float4 xv = src4[c4];
        n0 = fmaf(xv.x, xv.x, n0); n1 = fmaf(xv.y, xv.y, n1);
        n2 = fmaf(xv.z, xv.z, n2); n3 = fmaf(xv.w, xv.w, n3);
#pragma unroll
        for (int k = 0; k < 8; ++k) {
            const float* rk = &rs[k * HDIM + c4 * 4];
            dacc[k] = fmaf(xv.x, rk[0], dacc[k]);
            dacc[k] = fmaf(xv.y, rk[1], dacc[k]);
            dacc[k] = fmaf(xv.z, rk[2], dacc[k]);
            dacc[k] = fmaf(xv.w, rk[3], dacc[k]);
        }
    }
    float nrm = (n0 + n1) + (n2 + n3);
    unsigned int bits = 0;
#pragma unroll
    for (int k = 0; k < 8; ++k) bits |= (dacc[k] >= 0.f ? 1u : 0u) << k;
    int bhn = ((row >> 10) * HEADS + h) * NSEQ + (row & (NSEQ - 1));
    if (isK) { g_kh[bhn] = (unsigned char)bits; g_kn[bhn] = nrm; }
    else     { g_qh[bhn] = (unsigned char)bits; g_qn[bhn] = nrm; }
}

// ---------------- sparse hyperbolic attention (R13 structure + closed-form weight) ----------------
__global__ __launch_bounds__(128) void attn_kernel(int M)
{
    const int PER = NSEQ / 128;          // 8 contiguous j per thread
    int gid = blockIdx.x;
    int n  = gid & (NSEQ - 1);
    int bh = gid >> 10;
    int h = bh & 7, b = bh >> 3;

    const float* Q = g_QKV;
    const float* K = g_QKV + (size_t)M * D_MODEL;
    const float* V = g_QKV + 2 * (size_t)M * D_MODEL;

    __shared__ float sc[TOPK + 2];       // dots -> weights (pad slots 102/103)
    __shared__ short selj[TOPK];
    __shared__ int whist[4][10];         // [warp][bucket], slot 9 = dead pad
    __shared__ int wsum[4];              // packed (gt<<16 | eq) per warp
    __shared__ float wpart[8];           // per (warp, half) weight sums
    __shared__ __align__(16) float ored[8][HDIM];

    int tid = threadIdx.x, lane = tid & 31, warp = tid >> 5;
    int halfl = lane >> 4;               // V pass: which key of the pair
    int qlane = lane & 15;               // V pass: float4 chunk
    int grp = lane >> 3;                 // dot pass: group 0..3 (8 lanes each)
    int gl  = lane & 7;                  // dot pass: lane within group

    size_t rowbase = (size_t)b * NSEQ * D_MODEL + h * HDIM;
    const float* qrow = Q + rowbase + (size_t)n * D_MODEL;
    float4 qr0 = *reinterpret_cast<const float4*>(qrow + gl * 8);
    float4 qr1 = *reinterpret_cast<const float4*>(qrow + gl * 8 + 4);

    // --- hash match counts for my 8 contiguous keys ---
    unsigned int qb = g_qh[bh * NSEQ + n];
    float qn = g_qn[bh * NSEQ + n];
    const unsigned char* khb = g_kh + bh * NSEQ;
    int base = tid * PER;
    uint2 kv8 = *reinterpret_cast<const uint2*>(khb + base);
    int m[PER];
#pragma unroll
    for (int i = 0; i < PER; ++i) {
        unsigned int byte = ((i < 4 ? kv8.x >> (8 * i) : kv8.y >> (8 * (i - 4))) & 0xFFu);
        m[i] = 8 - __popc(byte ^ qb);
    }

    // --- packed per-warp histogram: buckets (2vp, 2vp+1) in one redux ---
#pragma unroll
    for (int vp = 0; vp < 5; ++vp) {
        int v0 = 2 * vp, v1 = 2 * vp + 1;   // v1==9 never matches (m<=8)
        int c = 0;
#pragma unroll
        for (int i = 0; i < PER; ++i) {
            c += (m[i] == v0) ? 0x10000 : 0;
            c += (m[i] == v1) ? 1 : 0;
        }
        c = __reduce_add_sync(0xffffffffu, c);
        if (lane == vp) {
            whist[warp][v0] = c >> 16;
            whist[warp][v1] = c & 0xFFFF;   // slot 9 = dead pad
        }
    }
    __syncthreads();   // (1) whist ready

    // --- uniform threshold in registers ---
    int t = 0, need = TOPK;
    {
        int cum = 0;
#pragma unroll
        for (int v = 8; v >= 0; --v) {
            int hv = whist[0][v] + whist[1][v] + whist[2][v] + whist[3][v];
            int ncum = cum + hv;
            if (cum < TOPK && ncum >= TOPK) { t = v; need = TOPK - cum; }
            cum = ncum;
        }
    }
    int ngt = TOPK - need;

    // --- packed selection scan: (cgt<<16 | ceq), one shuffle scan ---
    int cgt = 0, ceq = 0;
#pragma unroll
    for (int i = 0; i < PER; ++i) { cgt += (m[i] > t); ceq += (m[i] == t); }
    int pk = (cgt << 16) | ceq;
    int spk = pk;
#pragma unroll
    for (int o = 1; o < 32; o <<= 1) {
        int a = __shfl_up_sync(0xffffffffu, spk, o); if (lane >= o) spk += a;
    }
    if (lane == 31) wsum[warp] = spk;
    __syncthreads();   // (2) wsum ready
    int rank = spk - pk;
#pragma unroll
    for (int w = 0; w < 4; ++w) if (w < warp) rank += wsum[w];
    int rgt = rank >> 16, req = rank & 0xFFFF;
#pragma unroll
    for (int i = 0; i < PER; ++i) {
        int j = base + i;
        if (m[i] > t) selj[rgt++] = (short)j;
        else if (m[i] == t) { if (req < need) selj[ngt + req] = (short)j; req++; }
    }
    __syncthreads();   // (3) selj ready

    // --- coalesced dot pass: 8-lane group per key row, 3-shuffle reduce ---
    const float* Kb = K + rowbase;
#pragma unroll
    for (int i = 0; i < 7; ++i) {
        int s = (warp * 4 + grp) + 16 * i;   // 0..111, unique per (warp,grp,i)
        bool ok = (s < TOPK);
        int j = ok ? (int)selj[s] : 0;
        int joff = j << 9;                   // j * D_MODEL
        const float* kr = Kb + joff + gl * 8;
        float4 k0 = *reinterpret_cast<const float4*>(kr);
        float4 k1 = *reinterpret_cast<const float4*>(kr + 4);
        float part = fmaf(qr0.x, k0.x,
                     fmaf(qr0.y, k0.y,
                     fmaf(qr0.z, k0.z,
                     fmaf(qr0.w, k0.w,
                     fmaf(qr1.x, k1.x,
                     fmaf(qr1.y, k1.y,
                     fmaf(qr1.z, k1.z, qr1.w * k1.w)))))));
#pragma unroll
        for (int o = 1; o < 8; o <<= 1)
            part += __shfl_xor_sync(0xffffffffu, part, o);
        if (gl == 0) sc[ok ? s : TOPK] = part;   // dead-slot write for s>=TOPK
    }
    __syncthreads();   // (4) dots ready

    // --- score + weight, all threads parallel; closed-form exp(-acosh) ---
    if (tid < TOPK) {
        float dot = sc[tid];
        int j = selj[tid];
        float kn = g_kn[bh * NSEQ + j];
        float dsq = qn + kn - 2.f * dot;
        float denom = fmaxf((1.f - qn) * (1.f - kn), 1e-6f);
        float ca = fmaxf(1.f + 2.f * dsq / denom, 1.f);
        // exp(-acosh(ca)) == 1 / (ca + sqrt(ca^2 - 1)), exact
        sc[tid] = 1.f / (ca + sqrtf(fmaf(ca, ca, -1.f)));
    }
    __syncthreads();   // (5) weights ready

    // --- weighted V sum + weight-sum: half-warp per key row (proven form) ---
    const float* Vb = V + rowbase + qlane * 4;
    float4 acc = make_float4(0.f, 0.f, 0.f, 0.f);
    float wacc = 0.f;
#pragma unroll
    for (int i = 0; i < 13; ++i) {
        int p = warp + 4 * i;
        int s = 2 * p + halfl;
        bool ok = (s < TOPK);
        int j = ok ? (int)selj[s] : 0;
        int joff = j << 9;
        float w = ok ? sc[s] : 0.f;
        float4 v4 = *reinterpret_cast<const float4*>(Vb + joff);
        acc.x = fmaf(w, v4.x, acc.x);
        acc.y = fmaf(w, v4.y, acc.y);
        acc.z = fmaf(w, v4.z, acc.z);
        acc.w = fmaf(w, v4.w, acc.w);
        wacc += w;
    }
    *reinterpret_cast<float4*>(&ored[warp * 2 + halfl][qlane * 4]) = acc;
    if (qlane == 0) wpart[warp * 2 + halfl] = wacc;
    __syncthreads();   // (6) partials ready
    if (tid < HDIM) {
        float s0 = ored[0][tid] + ored[1][tid];
        float s1 = ored[2][tid] + ored[3][tid];
        float s2 = ored[4][tid] + ored[5][tid];
        float s3 = ored[6][tid] + ored[7][tid];
        float wt = ((wpart[0] + wpart[1]) + (wpart[2] + wpart[3]))
                 + ((wpart[4] + wpart[5]) + (wpart[6] + wpart[7]));
        g_att[((size_t)(b * NSEQ + n)) * D_MODEL + h * HDIM + tid] =
            ((s0 + s1) + (s2 + s3)) / wt;
    }
}

// ---------------- entry ----------------
extern "C" void kernel_launch(void* const* d_in, const int* in_sizes, int n_in,
                              void* d_out, int out_size)
{
    const float* x  = (const float*)d_in[0];
    const float* Wq = (const float*)d_in[1];
    const float* Wk = (const float*)d_in[2];
    const float* Wv = (const float*)d_in[3];
    const float* Wo = (const float*)d_in[4];
    const float* rv = (const float*)d_in[5];
    float* out = (float*)d_out;

    int M = in_sizes[0] / D_MODEL;   // B*N = 2048

    dim3 gq(M / GBM, (3 * D_MODEL) / GBN, 2); // (16, 12, 2) = 384 blocks
    gemm_qkv_kernel<<<gq, 256>>>(x, Wq, Wk, Wv, M);

    int nq4 = 3 * M * D_MODEL / 4;
    add_qkv_kernel<<<(nq4 + 255) / 256, 256>>>(nq4);

    int hthreads = 2 * M * HEADS;
    hash_kernel<<<(hthreads + 255) / 256, 256>>>(rv, M);

    attn_kernel<<<M * HEADS, 128>>>(M);       // 16384 blocks

    dim3 go(M / GBM, D_MODEL / GBN, 4);       // (16, 4, 4) = 256 blocks
    gemm_o_kernel<<<go, 256>>>(Wo, M);

    int n4 = M * D_MODEL / 4;
    add_kernel<<<(n4 + 255) / 256, 256>>>(out, n4);
}